// round 3
// baseline (speedup 1.0000x reference)
#include <cuda_runtime.h>
#include <cstdint>

// Problem constants
#define B_   64
#define S_   512
#define H_   768
#define P2_  46
#define KT   32
#define NKT  (H_ / KT)   // 24
#define MT   128         // rows per CTA (divides S_)

// Scratch (no cudaMalloc allowed)
__device__ float g_sdot[B_ * 48];
__device__ int   g_cue[B_];

// ---------------------------------------------------------------------------
// Prep kernel: per batch b compute
//   s[h]      = hs[b,id0,h] + hs[b,id1,h]
//   g_cue[b]  = sum(mask[b,:])
//   g_sdot[b,p] = dot(s, W[p])
// ---------------------------------------------------------------------------
__global__ void __launch_bounds__(128) prep_kernel(
    const float* __restrict__ hs, const int* __restrict__ ids,
    const int* __restrict__ mask, const float* __restrict__ W)
{
    __shared__ float s[H_];
    __shared__ int cue_sh;
    int b   = blockIdx.x;
    int tid = threadIdx.x;
    if (tid == 0) cue_sh = 0;
    __syncthreads();

    int id0 = ids[b * 2 + 0];
    int id1 = ids[b * 2 + 1];
    const float* h0 = hs + ((size_t)b * S_ + id0) * H_;
    const float* h1 = hs + ((size_t)b * S_ + id1) * H_;
    for (int h = tid; h < H_; h += 128) s[h] = h0[h] + h1[h];

    int local = 0;
    for (int t = tid; t < S_; t += 128) local += mask[b * S_ + t];
    #pragma unroll
    for (int o = 16; o; o >>= 1) local += __shfl_down_sync(0xffffffffu, local, o);
    if ((tid & 31) == 0) atomicAdd(&cue_sh, local);
    __syncthreads();

    int warp = tid >> 5, lane = tid & 31;
    for (int p = warp; p < P2_; p += 4) {
        const float* wp = W + (size_t)p * H_;
        float acc = 0.f;
        for (int h = lane; h < H_; h += 32) acc += s[h] * wp[h];
        #pragma unroll
        for (int o = 16; o; o >>= 1) acc += __shfl_down_sync(0xffffffffu, acc, o);
        if (lane == 0) g_sdot[b * 48 + p] = acc;
    }
    if (tid == 0) g_cue[b] = cue_sh;
}

// ---------------------------------------------------------------------------
// cp.async helpers
// ---------------------------------------------------------------------------
__device__ __forceinline__ void cpa16(float* dst, const float* src) {
    uint32_t sa = (uint32_t)__cvta_generic_to_shared(dst);
    asm volatile("cp.async.cg.shared.global [%0], [%1], 16;" :: "r"(sa), "l"(src));
}
__device__ __forceinline__ void cpa16z(float* dst, const float* src, int src_bytes) {
    uint32_t sa = (uint32_t)__cvta_generic_to_shared(dst);
    asm volatile("cp.async.cg.shared.global [%0], [%1], 16, %2;"
                 :: "r"(sa), "l"(src), "r"(src_bytes));
}
#define CP_COMMIT() asm volatile("cp.async.commit_group;")

// ---------------------------------------------------------------------------
// Main GEMM + fused epilogue kernel.
// 128 threads: n = tid&7 (cols j*8+n, j<6), m = tid>>3 (rows i*16+m, i<8).
// K pipelined in 2 cp.async stages of KT=32. Accumulate in packed f32x2.
// ---------------------------------------------------------------------------
__global__ void __launch_bounds__(128) main_kernel(
    const float* __restrict__ hs, const float* __restrict__ W,
    const float* __restrict__ bias, float* __restrict__ out)
{
    extern __shared__ float smem[];
    float* As = smem;                       // [2][128][36]
    float* Ws = smem + 2 * MT * 36;         // [2][48][36]

    const int tid = threadIdx.x;
    const int r0  = blockIdx.x * MT;        // first global row (b*512 + t)
    const int b   = r0 >> 9;
    const int n   = tid & 7;
    const int m   = tid >> 3;

    unsigned long long acc[8][6];
    #pragma unroll
    for (int i = 0; i < 8; i++)
        #pragma unroll
        for (int j = 0; j < 6; j++) acc[i][j] = 0ULL;

    // Global->smem load mapping: fr = tid>>3 (0..15), fk = (tid&7)*4
    const int fr = tid >> 3;
    const int fk = (tid & 7) * 4;

    auto load_stage = [&](int st, int k0) {
        float* Ab = As + st * MT * 36;
        float* Wb = Ws + st * 48 * 36;
        const float* gA = hs + ((size_t)(r0 + fr)) * H_ + k0 + fk;
        #pragma unroll
        for (int i = 0; i < 8; i++)
            cpa16(Ab + (fr + 16 * i) * 36 + fk, gA + (size_t)(16 * i) * H_);
        #pragma unroll
        for (int i = 0; i < 3; i++) {
            int nr = fr + 16 * i;  // 0..47
            const float* gW = (nr < P2_) ? (W + (size_t)nr * H_ + k0 + fk) : W;
            cpa16z(Wb + nr * 36 + fk, gW, (nr < P2_) ? 16 : 0);
        }
        CP_COMMIT();
    };

    load_stage(0, 0);

    for (int kt = 0; kt < NKT; ++kt) {
        if (kt + 1 < NKT) {
            load_stage((kt + 1) & 1, (kt + 1) * KT);
            asm volatile("cp.async.wait_group 1;");
        } else {
            asm volatile("cp.async.wait_group 0;");
        }
        __syncthreads();

        const int st = kt & 1;
        const float* Ab = As + st * MT * 36;
        const float* Wb = Ws + st * 48 * 36;

        #pragma unroll
        for (int k4 = 0; k4 < 8; ++k4) {
            const int k = k4 * 4;
            ulonglong2 af[8], bf[6];
            #pragma unroll
            for (int i = 0; i < 8; i++)
                af[i] = *(const ulonglong2*)(Ab + (i * 16 + m) * 36 + k);
            #pragma unroll
            for (int j = 0; j < 6; j++)
                bf[j] = *(const ulonglong2*)(Wb + (j * 8 + n) * 36 + k);
            #pragma unroll
            for (int i = 0; i < 8; i++)
                #pragma unroll
                for (int j = 0; j < 6; j++) {
                    asm("fma.rn.f32x2 %0, %1, %2, %0;"
                        : "+l"(acc[i][j]) : "l"(af[i].x), "l"(bf[j].x));
                    asm("fma.rn.f32x2 %0, %1, %2, %0;"
                        : "+l"(acc[i][j]) : "l"(af[i].y), "l"(bf[j].y));
                }
        }
        __syncthreads();
    }

    // Epilogue: logits = dot + bias + (t<cue)*sdot ; out = sigmoid(x)^4
    const int tbase = r0 & (S_ - 1);
    const int cue   = g_cue[b];
    #pragma unroll
    for (int j = 0; j < 6; j++) {
        const int col = j * 8 + n;
        if (col >= P2_) continue;
        const float bj  = bias[col];
        const float sdj = g_sdot[b * 48 + col];
        #pragma unroll
        for (int i = 0; i < 8; i++) {
            const int row = i * 16 + m;
            const int t   = tbase + row;
            float x = __uint_as_float((unsigned)acc[i][j])
                    + __uint_as_float((unsigned)(acc[i][j] >> 32));
            x += bj;
            if (t < cue) x += sdj;
            float sg  = 1.0f / (1.0f + __expf(-x));
            float sg2 = sg * sg;
            out[(size_t)(r0 + row) * P2_ + col] = sg2 * sg2;
        }
    }
}

// ---------------------------------------------------------------------------
// Launch
// ---------------------------------------------------------------------------
extern "C" void kernel_launch(void* const* d_in, const int* in_sizes, int n_in,
                              void* d_out, int out_size)
{
    const float* hs   = (const float*)d_in[0];  // [64,512,768] f32
    const int*   ids  = (const int*)  d_in[1];  // [64,2] i32
    const int*   mask = (const int*)  d_in[2];  // [64,512] i32
    const float* W    = (const float*)d_in[3];  // [46,768] f32
    const float* bias = (const float*)d_in[4];  // [46] f32
    float*       out  = (float*)d_out;          // [64,512,46] f32

    const int smem_bytes = (2 * MT * 36 + 2 * 48 * 36) * (int)sizeof(float); // 50688
    cudaFuncSetAttribute(main_kernel, cudaFuncAttributeMaxDynamicSharedMemorySize,
                         smem_bytes);

    prep_kernel<<<B_, 128>>>(hs, ids, mask, W);
    main_kernel<<<(B_ * S_) / MT, 128, smem_bytes>>>(hs, W, bias, out);
}

// round 5
// speedup vs baseline: 1.2080x; 1.2080x over previous
#include <cuda_runtime.h>
#include <cstdint>

// Problem constants
#define B_   64
#define S_   512
#define H_   768
#define P2_  46
#define KT   32
#define NKT  (H_ / KT)   // 24
#define MT   64          // rows per CTA (divides S_)
#define NST  3           // cp.async pipeline stages
#define AST  36          // smem row stride (floats), pad to kill conflicts

// Scratch (no cudaMalloc allowed)
__device__ float g_sdot[B_ * 48];
__device__ int   g_cue[B_];

// ---------------------------------------------------------------------------
// Prep kernel: per batch b compute
//   s[h]        = hs[b,id0,h] + hs[b,id1,h]
//   g_cue[b]    = sum(mask[b,:])
//   g_sdot[b,p] = dot(s, W[p])
// 256 threads, 8 warps; sdot inner loop fully unrolled for MLP.
// ---------------------------------------------------------------------------
__global__ void __launch_bounds__(256) prep_kernel(
    const float* __restrict__ hs, const int* __restrict__ ids,
    const int* __restrict__ mask, const float* __restrict__ W)
{
    __shared__ float s[H_];
    __shared__ int cue_sh;
    const int b   = blockIdx.x;
    const int tid = threadIdx.x;
    if (tid == 0) cue_sh = 0;
    __syncthreads();

    const int id0 = ids[b * 2 + 0];
    const int id1 = ids[b * 2 + 1];
    const float* h0 = hs + ((size_t)b * S_ + id0) * H_;
    const float* h1 = hs + ((size_t)b * S_ + id1) * H_;
    #pragma unroll
    for (int h = tid; h < H_; h += 256) s[h] = h0[h] + h1[h];

    int local = 0;
    #pragma unroll
    for (int t = tid; t < S_; t += 256) local += mask[b * S_ + t];
    #pragma unroll
    for (int o = 16; o; o >>= 1) local += __shfl_down_sync(0xffffffffu, local, o);
    if ((tid & 31) == 0) atomicAdd(&cue_sh, local);
    __syncthreads();

    const int warp = tid >> 5, lane = tid & 31;
    for (int p = warp; p < P2_; p += 8) {
        const float* wp = W + (size_t)p * H_;
        float acc = 0.f;
        #pragma unroll
        for (int h = 0; h < H_; h += 32) acc += s[h + lane] * __ldg(wp + h + lane);
        #pragma unroll
        for (int o = 16; o; o >>= 1) acc += __shfl_down_sync(0xffffffffu, acc, o);
        if (lane == 0) g_sdot[b * 48 + p] = acc;
    }
    if (tid == 0) g_cue[b] = cue_sh;
}

// ---------------------------------------------------------------------------
// cp.async helpers: .cg for streaming A (bypass L1), .ca for W (L1-resident,
// shared by the 4 co-resident CTAs on each SM).
// ---------------------------------------------------------------------------
__device__ __forceinline__ void cpa16_cg(float* dst, const float* src) {
    uint32_t sa = (uint32_t)__cvta_generic_to_shared(dst);
    asm volatile("cp.async.cg.shared.global [%0], [%1], 16;" :: "r"(sa), "l"(src));
}
__device__ __forceinline__ void cpa16_ca_z(float* dst, const float* src, int src_bytes) {
    uint32_t sa = (uint32_t)__cvta_generic_to_shared(dst);
    asm volatile("cp.async.ca.shared.global [%0], [%1], 16, %2;"
                 :: "r"(sa), "l"(src), "r"(src_bytes));
}
#define CP_COMMIT() asm volatile("cp.async.commit_group;")

// ---------------------------------------------------------------------------
// Main GEMM + fused epilogue.
// 128 threads: n = tid&7 (cols j*8+n, j<6), m = tid>>3 (rows i*16+m, i<4).
// 3-stage cp.async pipeline over K tiles of 32. Packed f32x2 accumulators.
// __launch_bounds__(128,4): 4 CTAs/SM -> 16 warps resident.
// ---------------------------------------------------------------------------
__global__ void __launch_bounds__(128, 4) main_kernel(
    const float* __restrict__ hs, const float* __restrict__ W,
    const float* __restrict__ bias, float* __restrict__ out)
{
    extern __shared__ float smem[];
    float* As = smem;                        // [NST][64][AST]
    float* Ws = smem + NST * MT * AST;       // [NST][48][AST]

    const int tid = threadIdx.x;
    const int r0  = blockIdx.x * MT;         // first global row (b*512 + t)
    const int b   = r0 >> 9;
    const int n   = tid & 7;
    const int m   = tid >> 3;

    unsigned long long acc[4][6];
    #pragma unroll
    for (int i = 0; i < 4; i++)
        #pragma unroll
        for (int j = 0; j < 6; j++) acc[i][j] = 0ULL;

    // Global->smem load mapping: fr = tid>>3 (0..15), fk = (tid&7)*4
    const int fr = tid >> 3;
    const int fk = (tid & 7) * 4;

    auto load_stage = [&](int st, int k0) {
        float* Ab = As + st * MT * AST;
        float* Wb = Ws + st * 48 * AST;
        const float* gA = hs + ((size_t)(r0 + fr)) * H_ + k0 + fk;
        #pragma unroll
        for (int i = 0; i < 4; i++)
            cpa16_cg(Ab + (fr + 16 * i) * AST + fk, gA + (size_t)(16 * i) * H_);
        #pragma unroll
        for (int i = 0; i < 3; i++) {
            int nr = fr + 16 * i;  // 0..47
            const float* gW = (nr < P2_) ? (W + (size_t)nr * H_ + k0 + fk) : W;
            cpa16_ca_z(Wb + nr * AST + fk, gW, (nr < P2_) ? 16 : 0);
        }
        CP_COMMIT();
    };

    load_stage(0, 0);
    load_stage(1, KT);

    for (int kt = 0; kt < NKT; ++kt) {
        // Safe to refill buffer (kt+2)%3 == (kt-1)%3: previous iteration ended
        // with __syncthreads after its compute.
        if (kt + 2 < NKT) {
            load_stage((kt + 2) % NST, (kt + 2) * KT);
            asm volatile("cp.async.wait_group 2;");   // stage kt complete
        } else if (kt + 1 < NKT) {
            asm volatile("cp.async.wait_group 1;");
        } else {
            asm volatile("cp.async.wait_group 0;");
        }
        __syncthreads();

        const int st = kt % NST;
        const float* Ab = As + st * MT * AST;
        const float* Wb = Ws + st * 48 * AST;

        #pragma unroll
        for (int k4 = 0; k4 < 8; ++k4) {
            const int k = k4 * 4;
            ulonglong2 af[4], bf[6];
            #pragma unroll
            for (int i = 0; i < 4; i++)
                af[i] = *(const ulonglong2*)(Ab + (i * 16 + m) * AST + k);
            #pragma unroll
            for (int j = 0; j < 6; j++)
                bf[j] = *(const ulonglong2*)(Wb + (j * 8 + n) * AST + k);
            #pragma unroll
            for (int i = 0; i < 4; i++)
                #pragma unroll
                for (int j = 0; j < 6; j++) {
                    asm("fma.rn.f32x2 %0, %1, %2, %0;"
                        : "+l"(acc[i][j]) : "l"(af[i].x), "l"(bf[j].x));
                    asm("fma.rn.f32x2 %0, %1, %2, %0;"
                        : "+l"(acc[i][j]) : "l"(af[i].y), "l"(bf[j].y));
                }
        }
        __syncthreads();
    }

    // Epilogue: logits = dot + bias + (t<cue)*sdot ; out = sigmoid(x)^4
    const int tbase = r0 & (S_ - 1);
    const int cue   = g_cue[b];
    #pragma unroll
    for (int j = 0; j < 6; j++) {
        const int col = j * 8 + n;
        if (col >= P2_) continue;
        const float bj  = bias[col];
        const float sdj = g_sdot[b * 48 + col];
        #pragma unroll
        for (int i = 0; i < 4; i++) {
            const int row = i * 16 + m;
            const int t   = tbase + row;
            float x = __uint_as_float((unsigned)acc[i][j])
                    + __uint_as_float((unsigned)(acc[i][j] >> 32));
            x += bj;
            if (t < cue) x += sdj;
            float sg  = 1.0f / (1.0f + __expf(-x));
            float sg2 = sg * sg;
            out[(size_t)(r0 + row) * P2_ + col] = sg2 * sg2;
        }
    }
}

// ---------------------------------------------------------------------------
// Launch
// ---------------------------------------------------------------------------
extern "C" void kernel_launch(void* const* d_in, const int* in_sizes, int n_in,
                              void* d_out, int out_size)
{
    const float* hs   = (const float*)d_in[0];  // [64,512,768] f32
    const int*   ids  = (const int*)  d_in[1];  // [64,2] i32
    const int*   mask = (const int*)  d_in[2];  // [64,512] i32
    const float* W    = (const float*)d_in[3];  // [46,768] f32
    const float* bias = (const float*)d_in[4];  // [46] f32
    float*       out  = (float*)d_out;          // [64,512,46] f32

    const int smem_bytes = NST * (MT * AST + 48 * AST) * (int)sizeof(float); // 48384
    cudaFuncSetAttribute(main_kernel, cudaFuncAttributeMaxDynamicSharedMemorySize,
                         smem_bytes);

    prep_kernel<<<B_, 256>>>(hs, ids, mask, W);
    main_kernel<<<(B_ * S_) / MT, 128, smem_bytes>>>(hs, W, bias, out);
}

// round 7
// speedup vs baseline: 1.7970x; 1.4876x over previous
#include <cuda_runtime.h>
#include <cuda_bf16.h>
#include <cstdint>

// Problem constants
#define B_   64
#define S_   512
#define H_   768
#define P2_  46
#define MT   64            // M rows per CTA
#define CK   32            // K elems per chunk
#define NCK  (H_ / CK)     // 24

// Smem stage layout (bytes). Rows padded to 80B (40 bf16): 16B-aligned for
// ldmatrix and 80*r mod 128 hits all eight 16B slots -> conflict-free.
#define A_HI 0
#define A_LO 5120          // 64*80
#define W_HI 10240
#define W_LO 14080         // +48*80
#define SS   17920
#define NT6  640           // 8 rows * 80B per n-tile

// Scratch (no cudaMalloc allowed)
__device__ float g_sdot[B_ * 48];
__device__ int   g_cue[B_];
__device__ __nv_bfloat16 g_wsplit[2][48 * H_];   // [hi|lo][48][768], rows 46-47 = 0

// ---------------------------------------------------------------------------
// W split-precision precompute: hi = bf16(x), lo = bf16(x - hi)
// ---------------------------------------------------------------------------
__global__ void __launch_bounds__(256) wconv_kernel(const float* __restrict__ W)
{
    const int idx = blockIdx.x * 256 + threadIdx.x;   // < 48*768 (exact grid)
    const int row = idx / H_;
    const float x = (row < P2_) ? W[idx] : 0.0f;
    __nv_bfloat16 hi = __float2bfloat16(x);
    __nv_bfloat16 lo = __float2bfloat16(x - __bfloat162float(hi));
    g_wsplit[0][idx] = hi;
    g_wsplit[1][idx] = lo;
}

// ---------------------------------------------------------------------------
// Prep: s = h[id0]+h[id1]; cue = sum(mask); sdot[p] = <s, W[p]>  (fp32)
// ---------------------------------------------------------------------------
__global__ void __launch_bounds__(256) prep_kernel(
    const float* __restrict__ hs, const int* __restrict__ ids,
    const int* __restrict__ mask, const float* __restrict__ W)
{
    __shared__ float s[H_];
    __shared__ int cue_sh;
    const int b = blockIdx.x, tid = threadIdx.x;
    if (tid == 0) cue_sh = 0;
    __syncthreads();

    const int id0 = ids[b * 2 + 0], id1 = ids[b * 2 + 1];
    const float* h0 = hs + ((size_t)b * S_ + id0) * H_;
    const float* h1 = hs + ((size_t)b * S_ + id1) * H_;
    #pragma unroll
    for (int h = tid; h < H_; h += 256) s[h] = h0[h] + h1[h];

    int local = 0;
    #pragma unroll
    for (int t = tid; t < S_; t += 256) local += mask[b * S_ + t];
    #pragma unroll
    for (int o = 16; o; o >>= 1) local += __shfl_down_sync(0xffffffffu, local, o);
    if ((tid & 31) == 0) atomicAdd(&cue_sh, local);
    __syncthreads();

    const int warp = tid >> 5, lane = tid & 31;
    for (int p = warp; p < P2_; p += 8) {
        const float* wp = W + (size_t)p * H_;
        float acc = 0.f;
        #pragma unroll
        for (int h = 0; h < H_; h += 32) acc += s[h + lane] * __ldg(wp + h + lane);
        #pragma unroll
        for (int o = 16; o; o >>= 1) acc += __shfl_down_sync(0xffffffffu, acc, o);
        if (lane == 0) g_sdot[b * 48 + p] = acc;
    }
    if (tid == 0) g_cue[b] = cue_sh;
}

// ---------------------------------------------------------------------------
// Warp-MMA helpers (base ISA: sm_80+, compiles on plain sm_103 target)
// ---------------------------------------------------------------------------
__device__ __forceinline__ void ldsm4(uint32_t* r, uint32_t addr) {
    asm volatile("ldmatrix.sync.aligned.m8n8.x4.shared.b16 {%0,%1,%2,%3}, [%4];"
                 : "=r"(r[0]), "=r"(r[1]), "=r"(r[2]), "=r"(r[3]) : "r"(addr));
}
__device__ __forceinline__ void ldsm2(uint32_t* r, uint32_t addr) {
    asm volatile("ldmatrix.sync.aligned.m8n8.x2.shared.b16 {%0,%1}, [%2];"
                 : "=r"(r[0]), "=r"(r[1]) : "r"(addr));
}
__device__ __forceinline__ void mma_bf16(float* c, const uint32_t* a,
                                         const uint32_t* b) {
    asm volatile(
        "mma.sync.aligned.m16n8k16.row.col.f32.bf16.bf16.f32 "
        "{%0,%1,%2,%3}, {%4,%5,%6,%7}, {%8,%9}, {%0,%1,%2,%3};"
        : "+f"(c[0]), "+f"(c[1]), "+f"(c[2]), "+f"(c[3])
        : "r"(a[0]), "r"(a[1]), "r"(a[2]), "r"(a[3]), "r"(b[0]), "r"(b[1]));
}
// pack two floats -> bf16x2 (first arg -> bits[31:16], second -> bits[15:0])
__device__ __forceinline__ uint32_t cvt2(float hiE, float loE) {
    uint32_t d;
    asm("cvt.rn.bf16x2.f32 %0, %1, %2;" : "=r"(d) : "f"(hiE), "f"(loE));
    return d;
}

// ---------------------------------------------------------------------------
// Main: split-precision bf16 mma.sync GEMM + fused epilogue.
// 512 CTAs x 128 threads. Warp w owns rows [w*16, w*16+16). N=48 (cols 46-47
// are junk from zeroed W rows; never stored). Double-buffered smem, one
// __syncthreads per K-chunk; LDG reg-prefetch one chunk ahead.
// ---------------------------------------------------------------------------
__global__ void __launch_bounds__(128) main_kernel(
    const float* __restrict__ hs, const float* __restrict__ bias,
    float* __restrict__ out)
{
    __shared__ __align__(16) char smem[2 * SS];
    const uint32_t sb = (uint32_t)__cvta_generic_to_shared(smem);
    const int tid = threadIdx.x, w = tid >> 5, l = tid & 31;
    const int r0 = blockIdx.x * MT, b = r0 >> 9;

    // --- LDG register staging ---
    float4 aReg[4];
    uint4  wReg[3];
    const int aRow0 = tid >> 3;          // + 16*i
    const int aQ    = tid & 7;           // float4 index within 32-col chunk

    auto loadA = [&](int ck) {
        const float* g = hs + (size_t)(r0 + aRow0) * H_ + ck * CK + aQ * 4;
        #pragma unroll
        for (int i = 0; i < 4; i++)
            aReg[i] = *(const float4*)(g + (size_t)(16 * i) * H_);
    };
    auto loadW = [&](int ck) {
        #pragma unroll
        for (int i = 0; i < 3; i++) {
            int g  = tid + i * 128;          // 0..383
            int p  = g / 192;                // hi/lo half
            int rr = (g % 192) >> 2;         // row 0..47
            int q  = g & 3;                  // 16B granule in row
            const __nv_bfloat16* src = &g_wsplit[p][rr * H_ + ck * CK + q * 8];
            wReg[i] = *(const uint4*)src;
        }
    };
    auto stsStage = [&](int buf) {
        char* sp = smem + buf * SS;
        #pragma unroll
        for (int i = 0; i < 4; i++) {
            float4 v = aReg[i];
            uint32_t hi01 = cvt2(v.y, v.x);
            uint32_t hi23 = cvt2(v.w, v.z);
            float h0 = __uint_as_float(hi01 << 16);
            float h1 = __uint_as_float(hi01 & 0xffff0000u);
            float h2 = __uint_as_float(hi23 << 16);
            float h3 = __uint_as_float(hi23 & 0xffff0000u);
            uint32_t lo01 = cvt2(v.y - h1, v.x - h0);
            uint32_t lo23 = cvt2(v.w - h3, v.z - h2);
            int off = (aRow0 + 16 * i) * 80 + aQ * 8;
            *(uint2*)(sp + A_HI + off) = make_uint2(hi01, hi23);
            *(uint2*)(sp + A_LO + off) = make_uint2(lo01, lo23);
        }
        #pragma unroll
        for (int i = 0; i < 3; i++) {
            int g  = tid + i * 128;
            int p  = g / 192;
            int rr = (g % 192) >> 2;
            int q  = g & 3;
            *(uint4*)(sp + W_HI + p * 3840 + rr * 80 + q * 16) = wReg[i];
        }
    };

    float acc[6][4];
    #pragma unroll
    for (int nt = 0; nt < 6; nt++)
        #pragma unroll
        for (int k = 0; k < 4; k++) acc[nt][k] = 0.f;

    loadA(0); loadW(0);

    // ldmatrix address components (fixed per thread)
    const int il = l & 15;
    const uint32_t aAddrBase = (uint32_t)((w * 16 + il) * 80 + (l >> 4) * 16);
    const uint32_t bAddrBase = (uint32_t)((il & 7) * 80 + (il >> 3) * 16);

    for (int ck = 0; ck < NCK; ck++) {
        const int buf = ck & 1;
        stsStage(buf);
        if (ck + 1 < NCK) { loadA(ck + 1); loadW(ck + 1); }
        __syncthreads();

        const uint32_t sbase = sb + buf * SS;
        #pragma unroll
        for (int ks = 0; ks < 2; ks++) {
            uint32_t ahi[4], alo[4];
            ldsm4(ahi, sbase + A_HI + aAddrBase + ks * 32);
            ldsm4(alo, sbase + A_LO + aAddrBase + ks * 32);
            #pragma unroll
            for (int nt = 0; nt < 6; nt++) {
                uint32_t bhi[2], blo[2];
                ldsm2(bhi, sbase + W_HI + nt * NT6 + bAddrBase + ks * 32);
                ldsm2(blo, sbase + W_LO + nt * NT6 + bAddrBase + ks * 32);
                mma_bf16(acc[nt], ahi, bhi);
                mma_bf16(acc[nt], ahi, blo);
                mma_bf16(acc[nt], alo, bhi);
            }
        }
        // No trailing barrier needed: next iteration's STS targets the other
        // buffer, separated from this buffer's readers by next __syncthreads.
    }

    // --- Epilogue: x = D + bias + (t<cue)*sdot ; out = sigmoid(x)^4 ---
    const int mrow = w * 16 + (l >> 2);          // row of c0/c1 (c2/c3: +8)
    const int cue  = g_cue[b];
    const int t0   = (r0 & (S_ - 1)) + mrow;
    const float f0 = (t0 < cue) ? 1.0f : 0.0f;
    const float f1 = (t0 + 8 < cue) ? 1.0f : 0.0f;
    float* o0 = out + (size_t)(r0 + mrow) * P2_;
    float* o1 = o0 + 8 * P2_;

    #pragma unroll
    for (int nt = 0; nt < 6; nt++) {
        const int col = nt * 8 + (l & 3) * 2;
        if (col >= P2_) continue;                // drops cols 46,47
        const float b0 = __ldg(bias + col),     b1 = __ldg(bias + col + 1);
        const float s0 = g_sdot[b * 48 + col],  s1 = g_sdot[b * 48 + col + 1];

        float x00 = acc[nt][0] + b0 + f0 * s0;
        float x01 = acc[nt][1] + b1 + f0 * s1;
        float x10 = acc[nt][2] + b0 + f1 * s0;
        float x11 = acc[nt][3] + b1 + f1 * s1;
        float g00 = 1.f / (1.f + __expf(-x00)); g00 *= g00; g00 *= g00;
        float g01 = 1.f / (1.f + __expf(-x01)); g01 *= g01; g01 *= g01;
        float g10 = 1.f / (1.f + __expf(-x10)); g10 *= g10; g10 *= g10;
        float g11 = 1.f / (1.f + __expf(-x11)); g11 *= g11; g11 *= g11;
        *(float2*)(o0 + col) = make_float2(g00, g01);
        *(float2*)(o1 + col) = make_float2(g10, g11);
    }
}

// ---------------------------------------------------------------------------
// Launch
// ---------------------------------------------------------------------------
extern "C" void kernel_launch(void* const* d_in, const int* in_sizes, int n_in,
                              void* d_out, int out_size)
{
    const float* hs   = (const float*)d_in[0];  // [64,512,768] f32
    const int*   ids  = (const int*)  d_in[1];  // [64,2] i32
    const int*   mask = (const int*)  d_in[2];  // [64,512] i32
    const float* W    = (const float*)d_in[3];  // [46,768] f32
    const float* bias = (const float*)d_in[4];  // [46] f32
    float*       out  = (float*)d_out;          // [64,512,46] f32

    wconv_kernel<<<(48 * H_) / 256, 256>>>(W);
    prep_kernel<<<B_, 256>>>(hs, ids, mask, W);
    main_kernel<<<(B_ * S_) / MT, 128>>>(hs, bias, out);
}

// round 8
// speedup vs baseline: 2.1228x; 1.1813x over previous
#include <cuda_runtime.h>
#include <cuda_bf16.h>
#include <cstdint>

// Problem constants
#define B_   64
#define S_   512
#define H_   768
#define P2_  46
#define MT   64            // M rows per CTA
#define CK   32            // K elems per chunk
#define NCK  (H_ / CK)     // 24

// B smem: per buffer {W_hi 48x80B, W_lo 48x80B}; 3 buffers.
// 80B row pitch: 16B-aligned and conflict-free for ldmatrix (offsets/16 mod 8
// cycle through all slots).
#define WB    3840         // 48*80: lo-half offset within buffer
#define WBUF  7680
#define NT6   640          // 8 rows * 80B per n-tile

// Scratch (no cudaMalloc allowed)
__device__ float g_sdot[B_ * 48];
__device__ int   g_cue[B_];
__device__ __nv_bfloat16 g_wsplit[2][48 * H_];   // [hi|lo][48][768], rows 46-47 = 0

// ---------------------------------------------------------------------------
// Combo kernel: blocks [0,144) = W split precompute; blocks [144,208) = prep.
//   wconv: hi = bf16(x), lo = bf16(x - hi)
//   prep:  s = h[id0]+h[id1]; cue = sum(mask); sdot[p] = <s, W[p]> (fp32)
// ---------------------------------------------------------------------------
__global__ void __launch_bounds__(256) combo_kernel(
    const float* __restrict__ hs, const int* __restrict__ ids,
    const int* __restrict__ mask, const float* __restrict__ W)
{
    __shared__ float s[H_];
    __shared__ int cue_sh;
    const int tid = threadIdx.x;

    if (blockIdx.x < 144) {
        const int idx = blockIdx.x * 256 + tid;      // < 48*768 exactly
        const int row = idx / H_;
        const float x = (row < P2_) ? W[idx] : 0.0f;
        __nv_bfloat16 hi = __float2bfloat16(x);
        __nv_bfloat16 lo = __float2bfloat16(x - __bfloat162float(hi));
        g_wsplit[0][idx] = hi;
        g_wsplit[1][idx] = lo;
        return;
    }

    const int b = blockIdx.x - 144;
    if (tid == 0) cue_sh = 0;
    __syncthreads();

    const int id0 = ids[b * 2 + 0], id1 = ids[b * 2 + 1];
    const float* h0 = hs + ((size_t)b * S_ + id0) * H_;
    const float* h1 = hs + ((size_t)b * S_ + id1) * H_;
    #pragma unroll
    for (int h = tid; h < H_; h += 256) s[h] = h0[h] + h1[h];

    int local = 0;
    #pragma unroll
    for (int t = tid; t < S_; t += 256) local += mask[b * S_ + t];
    #pragma unroll
    for (int o = 16; o; o >>= 1) local += __shfl_down_sync(0xffffffffu, local, o);
    if ((tid & 31) == 0) atomicAdd(&cue_sh, local);
    __syncthreads();

    const int warp = tid >> 5, lane = tid & 31;
    for (int p = warp; p < P2_; p += 8) {
        const float* wp = W + (size_t)p * H_;
        float acc = 0.f;
        #pragma unroll
        for (int h = 0; h < H_; h += 32) acc += s[h + lane] * __ldg(wp + h + lane);
        #pragma unroll
        for (int o = 16; o; o >>= 1) acc += __shfl_down_sync(0xffffffffu, acc, o);
        if (lane == 0) g_sdot[b * 48 + p] = acc;
    }
    if (tid == 0) g_cue[b] = cue_sh;
}

// ---------------------------------------------------------------------------
// Warp-MMA helpers (base ISA, compiles on plain sm_103 target)
// ---------------------------------------------------------------------------
__device__ __forceinline__ void ldsm4(uint32_t* r, uint32_t addr) {
    asm volatile("ldmatrix.sync.aligned.m8n8.x4.shared.b16 {%0,%1,%2,%3}, [%4];"
                 : "=r"(r[0]), "=r"(r[1]), "=r"(r[2]), "=r"(r[3]) : "r"(addr));
}
__device__ __forceinline__ void mma_bf16(float* c, const uint32_t* a,
                                         const uint32_t* b) {
    asm volatile(
        "mma.sync.aligned.m16n8k16.row.col.f32.bf16.bf16.f32 "
        "{%0,%1,%2,%3}, {%4,%5,%6,%7}, {%8,%9}, {%0,%1,%2,%3};"
        : "+f"(c[0]), "+f"(c[1]), "+f"(c[2]), "+f"(c[3])
        : "r"(a[0]), "r"(a[1]), "r"(a[2]), "r"(a[3]), "r"(b[0]), "r"(b[1]));
}
// pack two floats -> bf16x2 (first arg -> bits[31:16], second -> bits[15:0])
__device__ __forceinline__ uint32_t cvt2(float hiE, float loE) {
    uint32_t d;
    asm("cvt.rn.bf16x2.f32 %0, %1, %2;" : "=r"(d) : "f"(hiE), "f"(loE));
    return d;
}
__device__ __forceinline__ void cpa16(uint32_t dst, const void* src) {
    asm volatile("cp.async.ca.shared.global [%0], [%1], 16;"
                 :: "r"(dst), "l"(src));
}

// ---------------------------------------------------------------------------
// Main: split-precision bf16 mma.sync GEMM + fused epilogue.
// A path: LDG.64 -> convert -> mma fragments directly in registers (no smem).
//   Fragment layout (m16n8k16 row-major A): thread l of warp w holds
//   a0=(r,2c),(r,2c+1)  a1=(r+8,..)  a2=(r,2c+8),(r,2c+9)  a3=(r+8,..)
//   with r = w*16 + l/4, c = l&3; low 16 bits = even column.
// B path: cp.async from pre-split g_wsplit into 3-stage smem ring; ldmatrix x4
// loads two n-tiles per instruction. D = Ah*Wh + Ah*Wl + Al*Wh.
// ---------------------------------------------------------------------------
__global__ void __launch_bounds__(128) main_kernel(
    const float* __restrict__ hs, const float* __restrict__ bias,
    float* __restrict__ out)
{
    __shared__ __align__(16) char smem[3 * WBUF];
    const uint32_t sb = (uint32_t)__cvta_generic_to_shared(smem);
    const int tid = threadIdx.x, w = tid >> 5, l = tid & 31;
    const int r0 = blockIdx.x * MT, b = r0 >> 9;

    // --- B producer: 384 x 16B segments per chunk, 3 per thread ---
    auto cpB = [&](int ck) {
        const int buf = ck % 3;
        #pragma unroll
        for (int i = 0; i < 3; i++) {
            int g  = tid + i * 128;
            int p  = g / 192;            // hi/lo half
            int rr = (g % 192) >> 2;     // row 0..47
            int q  = g & 3;              // 16B granule
            cpa16(sb + buf * WBUF + p * WB + rr * 80 + q * 16,
                  &g_wsplit[p][rr * H_ + ck * CK + q * 8]);
        }
        asm volatile("cp.async.commit_group;");
    };

    // --- A: direct-to-fragment loads ---
    const int ar = w * 16 + (l >> 2);
    const int ac = (l & 3) * 2;
    const float* gA0 = hs + (size_t)(r0 + ar) * H_ + ac;
    const float* gA1 = gA0 + 8 * H_;
    float2 aF[8];                        // [ks*4 + j], j = frag reg index
    auto ldA = [&](int ck) {
        #pragma unroll
        for (int ks = 0; ks < 2; ks++) {
            const int kb = ck * CK + ks * 16;
            aF[ks * 4 + 0] = *(const float2*)(gA0 + kb);
            aF[ks * 4 + 1] = *(const float2*)(gA1 + kb);
            aF[ks * 4 + 2] = *(const float2*)(gA0 + kb + 8);
            aF[ks * 4 + 3] = *(const float2*)(gA1 + kb + 8);
        }
    };

    float acc[6][4];
    #pragma unroll
    for (int nt = 0; nt < 6; nt++)
        #pragma unroll
        for (int k = 0; k < 4; k++) acc[nt][k] = 0.f;

    cpB(0); cpB(1);
    ldA(0);

    // ldmatrix x4 B address: lanes 0-15 -> n-tile nt, lanes 16-31 -> nt+1
    const int il = l & 15;
    const uint32_t bA = (uint32_t)((il & 7) * 80 + (il >> 3) * 16 + (l >> 4) * NT6);

    for (int ck = 0; ck < NCK; ck++) {
        if (ck + 1 < NCK)
            asm volatile("cp.async.wait_group 1;" ::: "memory");
        else
            asm volatile("cp.async.wait_group 0;" ::: "memory");
        __syncthreads();                 // B(ck) visible to all; ck-1 reads done
        if (ck + 2 < NCK) cpB(ck + 2);   // safe: buffer's readers were iter ck-1

        // Convert current A to hi/lo fragments, then prefetch next chunk's A.
        uint32_t ahi[8], alo[8];
        #pragma unroll
        for (int f = 0; f < 8; f++) {
            uint32_t h = cvt2(aF[f].y, aF[f].x);
            float h0 = __uint_as_float(h << 16);
            float h1 = __uint_as_float(h & 0xffff0000u);
            alo[f] = cvt2(aF[f].y - h1, aF[f].x - h0);
            ahi[f] = h;
        }
        if (ck + 1 < NCK) ldA(ck + 1);

        const uint32_t sbase = sb + (ck % 3) * WBUF;
        #pragma unroll
        for (int ks = 0; ks < 2; ks++) {
            const uint32_t* ah = ahi + ks * 4;
            const uint32_t* al = alo + ks * 4;
            #pragma unroll
            for (int pp = 0; pp < 3; pp++) {   // n-tile pairs (0,1)(2,3)(4,5)
                uint32_t bh[4], bl[4];
                const uint32_t ba = sbase + pp * 2 * NT6 + bA + ks * 32;
                ldsm4(bh, ba);
                ldsm4(bl, ba + WB);
                mma_bf16(acc[2 * pp],     ah, bh);
                mma_bf16(acc[2 * pp],     ah, bl + 0);   // lo of tile 2pp
                mma_bf16(acc[2 * pp],     al, bh);
                mma_bf16(acc[2 * pp + 1], ah, bh + 2);
                mma_bf16(acc[2 * pp + 1], ah, bl + 2);
                mma_bf16(acc[2 * pp + 1], al, bh + 2);
            }
        }
    }

    // --- Epilogue: x = D + bias + (t<cue)*sdot ; out = sigmoid(x)^4 ---
    const int mrow = w * 16 + (l >> 2);          // row of c0/c1 (c2/c3: +8)
    const int cue  = g_cue[b];
    const int t0   = (r0 & (S_ - 1)) + mrow;
    const float f0 = (t0 < cue) ? 1.0f : 0.0f;
    const float f1 = (t0 + 8 < cue) ? 1.0f : 0.0f;
    float* o0 = out + (size_t)(r0 + mrow) * P2_;
    float* o1 = o0 + 8 * P2_;

    #pragma unroll
    for (int nt = 0; nt < 6; nt++) {
        const int col = nt * 8 + (l & 3) * 2;
        if (col >= P2_) continue;                // drops cols 46,47
        const float b0 = __ldg(bias + col),     b1 = __ldg(bias + col + 1);
        const float s0 = g_sdot[b * 48 + col],  s1 = g_sdot[b * 48 + col + 1];

        float x00 = acc[nt][0] + b0 + f0 * s0;
        float x01 = acc[nt][1] + b1 + f0 * s1;
        float x10 = acc[nt][2] + b0 + f1 * s0;
        float x11 = acc[nt][3] + b1 + f1 * s1;
        float g00 = 1.f / (1.f + __expf(-x00)); g00 *= g00; g00 *= g00;
        float g01 = 1.f / (1.f + __expf(-x01)); g01 *= g01; g01 *= g01;
        float g10 = 1.f / (1.f + __expf(-x10)); g10 *= g10; g10 *= g10;
        float g11 = 1.f / (1.f + __expf(-x11)); g11 *= g11; g11 *= g11;
        *(float2*)(o0 + col) = make_float2(g00, g01);
        *(float2*)(o1 + col) = make_float2(g10, g11);
    }
}

// ---------------------------------------------------------------------------
// Launch
// ---------------------------------------------------------------------------
extern "C" void kernel_launch(void* const* d_in, const int* in_sizes, int n_in,
                              void* d_out, int out_size)
{
    const float* hs   = (const float*)d_in[0];  // [64,512,768] f32
    const int*   ids  = (const int*)  d_in[1];  // [64,2] i32
    const int*   mask = (const int*)  d_in[2];  // [64,512] i32
    const float* W    = (const float*)d_in[3];  // [46,768] f32
    const float* bias = (const float*)d_in[4];  // [46] f32
    float*       out  = (float*)d_out;          // [64,512,46] f32

    combo_kernel<<<144 + B_, 256>>>(hs, ids, mask, W);
    main_kernel<<<(B_ * S_) / MT, 128>>>(hs, bias, out);
}